// round 15
// baseline (speedup 1.0000x reference)
#include <cuda_runtime.h>
#include <cuda_fp16.h>
#include <cstdint>
#include <mma.h>

using namespace nvcuda;

// Problem constants (GCN_48473000903499): N=50000, D=64, L=3, OUT=16, E=800000
#define NN   50000
#define DD   64
#define OUTK 16
#define EE   800000
#define NE   (EE + NN)            // edges + self loops = 850000
#define NEP  (NE + 15 * NN)       // CSR capacity with per-row pad-to-16
#define NM   (NN * DD)            // 3,200,000 flat elements
#define NH2  (NN * 32)            // half2 count of real rows
#define NH2P ((NN + 1) * 32)      // + one zero pad row (index NN)
#define LDS_PAD 72                // smem row stride (halves / floats)
#define STAG_H 72                 // staging row stride in halves (144 B)

// ---- scratch (device globals; no allocation allowed) ----
// g_ints: [0,NN) deg_out(edges), [NN,2NN) deg_in(edges)->padded row len, [2NN] alloc counter
__device__ int     g_ints[2 * NN + 1];
__device__ int     g_off[NN];
__device__ int     g_cursor[NN];
__device__ int     g_csr_src[NEP];
__device__ float   g_norm_src[NN];
__device__ float   g_norm_dst[NN];
__device__ __align__(16) __half2 g_ha[NH2P];   // fp16 feature ping (row NN = zeros)
__device__ __align__(16) __half2 g_hb[NH2P];   // fp16 feature pong (row NN = zeros)
__device__ __align__(16) __half  g_wh[3 * DD * DD];  // fp16-converted gcn_w
__device__ float   g_xf[NM];       // final-layer fp32 output (FC input)

__device__ __forceinline__ void cp16(uint32_t dst, const void* src) {
    asm volatile("cp.async.cg.shared.global [%0], [%1], 16;\n" :: "r"(dst), "l"(src));
}
#define CP_COMMIT() asm volatile("cp.async.commit_group;\n" ::: "memory")
#define CP_WAIT0()  asm volatile("cp.async.wait_group 0;\n" ::: "memory")

// ---------------------------------------------------------------------------
// 1. histogram edges (deg arrays pre-zeroed by memset)
__global__ void k_hist(const int* __restrict__ src, const int* __restrict__ dst) {
    int e = blockIdx.x * blockDim.x + threadIdx.x;
    if (e < EE) {
        atomicAdd(&g_ints[src[e]], 1);          // deg_out
        atomicAdd(&g_ints[NN + dst[e]], 1);     // deg_in
    }
}

// 2. per-node: norms (+1 self loop), pad-16 CSR slot alloc, pad-fill with zero-row
//    index NN, bias init, zero pad feature rows, and fp16-convert gcn_w (once).
__global__ void k_build(const float* __restrict__ fc_b, float* __restrict__ out,
                        const float* __restrict__ gcn_w) {
    int i = blockIdx.x * blockDim.x + threadIdx.x;
    if (i < NN) {
        int dout = g_ints[i] + 1;
        int din  = g_ints[NN + i] + 1;          // entries incl. self loop
        g_norm_src[i] = rsqrtf((float)dout);
        g_norm_dst[i] = rsqrtf((float)din);
        int dpad = (din + 15) & ~15;            // pad to 16 (wmma chunk)
        int off = atomicAdd(&g_ints[2 * NN], dpad);
        g_off[i] = off;
        g_cursor[i] = off;
        g_ints[NN + i] = dpad;                  // repurpose: padded row length
        for (int p = off + din; p < off + dpad; p++) g_csr_src[p] = NN;
    }
    if (blockIdx.x == 0) {
        if (threadIdx.x < OUTK) out[threadIdx.x] = fc_b[threadIdx.x];
        if (threadIdx.x >= 32 && threadIdx.x < 64) {   // zero pad rows
            int l = threadIdx.x - 32;
            g_ha[NN * 32 + l] = __floats2half2_rn(0.f, 0.f);
            g_hb[NN * 32 + l] = __floats2half2_rn(0.f, 0.f);
        }
    }
    // blocks 100..147: convert 3*64*64 = 12288 W entries to fp16
    if (blockIdx.x >= 100 && blockIdx.x < 148) {
        int wi = (blockIdx.x - 100) * 256 + threadIdx.x;
        g_wh[wi] = __float2half(gcn_w[wi]);
    }
}

// 3. fused: scatter edges+loops into CSR, and premul F*norm_src -> fp16 ha
__global__ void k_scatpre(const int* __restrict__ src, const int* __restrict__ dst,
                          const float* __restrict__ F) {
    int i = blockIdx.x * blockDim.x + threadIdx.x;
    if (i < NE) {
        if (i < EE) {
            int d = dst[i];
            int p = atomicAdd(&g_cursor[d], 1);
            g_csr_src[p] = src[i];
        } else {
            int n = i - EE;
            int p = atomicAdd(&g_cursor[n], 1);
            g_csr_src[p] = n;
        }
    } else {
        int j = i - NE;                         // half2 index
        if (j < NH2) {
            float2 f = ((const float2*)F)[j];
            float ns = g_norm_src[j >> 5];
            g_ha[j] = __floats2half2_rn(f.x * ns, f.y * ns);
        }
    }
}

// 4. fused SpMM + GEMM, all-tensor-core. 64 nodes/block, 8 warps.
//    Phase A: cp.async stages 16 gathered rows (2KB) into per-warp smem, then
//    one wmma pass with a selector-A (row it = ones) accumulates the row-sum
//    for node `it` into fp32 C fragments. No register staging, no conversions.
//    Phase B/C: 64x64x64 HMMA GEMM + bias/relu epilogue as before.
struct SmemL {
    __half Wh[DD][LDS_PAD];            // 9216 B
    __half Aones[8][16][16];           // 4096 B  selector patterns
    __half aggh[DD][LDS_PAD];          // 9216 B
    float  bsh[DD];                    // 256 B
    union {
        __half stag[8][16][STAG_H];    // 18432 B (per-warp 16x144B staging)
        float  outS[DD][LDS_PAD];      // 18432 B (phase C)
    } u;
};

template <bool HALF_OUT>
__global__ void __launch_bounds__(256) k_layer(
    const __half2* __restrict__ x2, const __half* __restrict__ Wh16,
    const float* __restrict__ b, __half2* __restrict__ yh, float* __restrict__ yf)
{
    __shared__ SmemL sm;

    int tid = threadIdx.x;
    int warp = tid >> 5, lane = tid & 31;
    int nodeBase = blockIdx.x * 64;

    // W tile: fp16 copy, vectorized uint2 (8B) to respect padded row stride
    {
        const uint2* ws = (const uint2*)Wh16;
        for (int i = tid; i < DD * DD / 4; i += 256) {
            uint2 u = ws[i];
            *(uint2*)&sm.Wh[i >> 4][(i * 4) & 63] = u;
        }
    }
    // selector patterns: Aones[m] has row m = ones, else zeros
    for (int i = tid; i < 8 * 256; i += 256) {
        int m = i >> 8, r = (i >> 4) & 15;
        ((__half*)sm.Aones)[i] = (r == m) ? __float2half(1.f) : __float2half(0.f);
    }
    if (tid < DD) sm.bsh[tid] = b[tid];

    // lane-parallel preload: lanes 0-7 offsets+lens, 16-23 dst-norms
    int group = nodeBase + warp * 8;
    int offv = 0, lenv = 0; float ndv = 0.f;
    if (lane < 8 && group + lane < NN) {
        offv = g_off[group + lane];
        lenv = g_ints[NN + group + lane];
    }
    if (lane >= 16 && lane < 24 && group + lane - 16 < NN)
        ndv = g_norm_dst[group + lane - 16];
    __syncthreads();

    // ---- Phase A: tensor-core segmented row-sum ----
    const char* xb = (const char*)x2;          // row = 128 B
    int rowgrp = lane >> 3;                    // 0..3
    int chunk8 = lane & 7;                     // 16B chunk within row
    uint32_t stagbase =
        (uint32_t)__cvta_generic_to_shared(&sm.u.stag[warp][0][0]) + chunk8 * 16;

    wmma::fragment<wmma::accumulator, 16, 16, 16, float> C0, C1, C2, C3;
    wmma::fill_fragment(C0, 0.f); wmma::fill_fragment(C1, 0.f);
    wmma::fill_fragment(C2, 0.f); wmma::fill_fragment(C3, 0.f);

    #pragma unroll 1
    for (int it = 0; it < 8; it++) {
        int s0  = __shfl_sync(0xffffffffu, offv, it);
        int len = __shfl_sync(0xffffffffu, lenv, it);   // multiple of 16 (0 if OOB)
        wmma::fragment<wmma::matrix_a, 16, 16, 16, __half, wmma::row_major> aF;
        wmma::load_matrix_sync(aF, &sm.Aones[it][0][0], 16);

        #pragma unroll 1
        for (int base = 0; base < len; base += 32) {
            int rem = len - base;
            int s = (lane < rem) ? g_csr_src[s0 + base + lane] : NN;
            int nch = (rem < 32 ? rem : 32) >> 4;       // 1 or 2 chunks of 16 rows
            #pragma unroll 1
            for (int c = 0; c < nch; c++) {
                #pragma unroll
                for (int q = 0; q < 4; q++) {
                    int ss = __shfl_sync(0xffffffffu, s, c * 16 + q * 4 + rowgrp);
                    cp16(stagbase + (q * 4 + rowgrp) * (STAG_H * 2),
                         xb + (size_t)ss * 128 + chunk8 * 16);
                }
                CP_COMMIT();
                CP_WAIT0();
                __syncwarp();
                wmma::fragment<wmma::matrix_b, 16, 16, 16, __half, wmma::row_major> bF;
                wmma::load_matrix_sync(bF, &sm.u.stag[warp][0][0],  STAG_H);
                wmma::mma_sync(C0, aF, bF, C0);
                wmma::load_matrix_sync(bF, &sm.u.stag[warp][0][16], STAG_H);
                wmma::mma_sync(C1, aF, bF, C1);
                wmma::load_matrix_sync(bF, &sm.u.stag[warp][0][32], STAG_H);
                wmma::mma_sync(C2, aF, bF, C2);
                wmma::load_matrix_sync(bF, &sm.u.stag[warp][0][48], STAG_H);
                wmma::mma_sync(C3, aF, bF, C3);
                __syncwarp();   // frags read before next chunk overwrites staging
            }
        }
    }

    // dump C (rows 0-7 = this warp's 8 nodes) -> aggh fp16 with dst-norm folded
    float* stagF = (float*)&sm.u.stag[warp][0][0];   // 16 x 36 floats view
    #pragma unroll
    for (int pair = 0; pair < 2; pair++) {
        __syncwarp();
        if (pair == 0) {
            wmma::store_matrix_sync(stagF,      C0, 36, wmma::mem_row_major);
            wmma::store_matrix_sync(stagF + 16, C1, 36, wmma::mem_row_major);
        } else {
            wmma::store_matrix_sync(stagF,      C2, 36, wmma::mem_row_major);
            wmma::store_matrix_sync(stagF + 16, C3, 36, wmma::mem_row_major);
        }
        __syncwarp();
        #pragma unroll
        for (int k = 0; k < 8; k++) {
            int idx = lane * 8 + k;
            int r = idx >> 5, ccol = idx & 31;     // r in 0..7
            float nd = __shfl_sync(0xffffffffu, ndv, 16 + r);
            sm.aggh[warp * 8 + r][pair * 32 + ccol] =
                __float2half_rn(stagF[r * 36 + ccol] * nd);
        }
    }
    __syncthreads();

    // ---- Phase B: 64x64x64 GEMM via HMMA (C kept in regs across barrier) ----
    int mi = warp >> 1;                // m-strip 0..3 (16 rows each)
    int n0 = (warp & 1) * 2;           // n-tile pair: tiles n0, n0+1

    wmma::fragment<wmma::accumulator, 16, 16, 16, float> cF0, cF1;
    wmma::fill_fragment(cF0, 0.f);
    wmma::fill_fragment(cF1, 0.f);
    #pragma unroll
    for (int k = 0; k < 4; k++) {
        wmma::fragment<wmma::matrix_a, 16, 16, 16, __half, wmma::row_major> aF;
        wmma::load_matrix_sync(aF, &sm.aggh[mi * 16][k * 16], LDS_PAD);
        wmma::fragment<wmma::matrix_b, 16, 16, 16, __half, wmma::row_major> bF;
        wmma::load_matrix_sync(bF, &sm.Wh[k * 16][n0 * 16], LDS_PAD);
        wmma::mma_sync(cF0, aF, bF, cF0);
        wmma::load_matrix_sync(bF, &sm.Wh[k * 16][(n0 + 1) * 16], LDS_PAD);
        wmma::mma_sync(cF1, aF, bF, cF1);
    }
    __syncthreads();    // staging fully read; smem union now becomes outS
    wmma::store_matrix_sync(&sm.u.outS[mi * 16][n0 * 16], cF0, LDS_PAD,
                            wmma::mem_row_major);
    wmma::store_matrix_sync(&sm.u.outS[mi * 16][(n0 + 1) * 16], cF1, LDS_PAD,
                            wmma::mem_row_major);
    __syncthreads();

    // ---- Phase C: epilogue ----
    int c0 = lane * 2;
    #pragma unroll 1
    for (int r = warp * 8; r < warp * 8 + 8; r++) {
        int node = nodeBase + r;
        if (node >= NN) break;
        float o0 = fmaxf(sm.u.outS[r][c0]     + sm.bsh[c0],     0.f);
        float o1 = fmaxf(sm.u.outS[r][c0 + 1] + sm.bsh[c0 + 1], 0.f);
        if (HALF_OUT) {
            float ns = g_norm_src[node];
            yh[node * 32 + lane] = __floats2half2_rn(o0 * ns, o1 * ns);
        } else {
            *(float2*)&yf[node * DD + c0] = make_float2(o0, o1);
        }
    }
}

// 5. out += fc_w @ relu(flat)   (DRAM-streaming GEMV; fc_w streamed evict-first)
__global__ void __launch_bounds__(256) k_fc(
    const float* __restrict__ fc_w, const float* __restrict__ xflat,
    float* __restrict__ out)
{
    __shared__ float sh[OUTK];
    if (threadIdx.x < OUTK) sh[threadIdx.x] = 0.f;
    __syncthreads();

    const int nv = NM / 4;  // 800000 float4s per output row
    float acc[OUTK];
    #pragma unroll
    for (int o = 0; o < OUTK; o++) acc[o] = 0.f;

    const float4* w4 = (const float4*)fc_w;
    const float4* x4 = (const float4*)xflat;
    int stride = gridDim.x * blockDim.x;
    for (int i = blockIdx.x * blockDim.x + threadIdx.x; i < nv; i += stride) {
        float4 f = x4[i];
        f.x = fmaxf(f.x, 0.f); f.y = fmaxf(f.y, 0.f);
        f.z = fmaxf(f.z, 0.f); f.w = fmaxf(f.w, 0.f);
        #pragma unroll
        for (int o = 0; o < OUTK; o++) {
            float4 w = __ldcs(&w4[(size_t)o * nv + i]);
            acc[o] = fmaf(w.x, f.x, acc[o]);
            acc[o] = fmaf(w.y, f.y, acc[o]);
            acc[o] = fmaf(w.z, f.z, acc[o]);
            acc[o] = fmaf(w.w, f.w, acc[o]);
        }
    }

    #pragma unroll
    for (int o = 0; o < OUTK; o++) {
        float v = acc[o];
        #pragma unroll
        for (int s = 16; s; s >>= 1) v += __shfl_xor_sync(0xffffffffu, v, s);
        if ((threadIdx.x & 31) == 0) atomicAdd(&sh[o], v);
    }
    __syncthreads();
    if (threadIdx.x < OUTK) atomicAdd(&out[threadIdx.x], sh[threadIdx.x]);
}

// ---------------------------------------------------------------------------
extern "C" void kernel_launch(void* const* d_in, const int* in_sizes, int n_in,
                              void* d_out, int out_size)
{
    const float* F     = (const float*)d_in[0];
    const int*   src   = (const int*)d_in[1];
    const int*   dst   = (const int*)d_in[2];
    const float* gcn_w = (const float*)d_in[3];
    const float* gcn_b = (const float*)d_in[4];
    const float* fc_w  = (const float*)d_in[5];
    const float* fc_b  = (const float*)d_in[6];
    float* out = (float*)d_out;

    void* ints_addr;   cudaGetSymbolAddress(&ints_addr, g_ints);
    __half2* ha; cudaGetSymbolAddress((void**)&ha, g_ha);
    __half2* hb; cudaGetSymbolAddress((void**)&hb, g_hb);
    __half*  wh; cudaGetSymbolAddress((void**)&wh, g_wh);
    float*   xf; cudaGetSymbolAddress((void**)&xf, g_xf);

    // graph prep
    cudaMemsetAsync(ints_addr, 0, (2 * NN + 1) * sizeof(int));
    k_hist<<<(EE + 255) / 256, 256>>>(src, dst);
    k_build<<<(NN + 255) / 256, 256>>>(fc_b, out, gcn_w);
    k_scatpre<<<(NE + NH2 + 255) / 256, 256>>>(src, dst, F);

    // 3 GCN layers: ha -> hb -> ha -> xf (fp32)
    const int lblocks = (NN + 63) / 64;
    k_layer<true ><<<lblocks, 256>>>(ha, wh + 0 * DD * DD, gcn_b + 0 * DD, hb, nullptr);
    k_layer<true ><<<lblocks, 256>>>(hb, wh + 1 * DD * DD, gcn_b + 1 * DD, ha, nullptr);
    k_layer<false><<<lblocks, 256>>>(ha, wh + 2 * DD * DD, gcn_b + 2 * DD, nullptr, xf);

    // FC head
    k_fc<<<1563, 256>>>(fc_w, xf, out);
}

// round 16
// speedup vs baseline: 7.1593x; 7.1593x over previous
#include <cuda_runtime.h>
#include <cuda_fp16.h>
#include <cstdint>
#include <mma.h>

using namespace nvcuda;

// Problem constants (GCN_48473000903499): N=50000, D=64, L=3, OUT=16, E=800000
#define NN   50000
#define DD   64
#define OUTK 16
#define EE   800000
#define NE   (EE + NN)            // edges + self loops = 850000
#define NEP  (NE + 7 * NN)        // CSR capacity with per-row pad-to-8
#define NM   (NN * DD)            // 3,200,000 flat elements
#define NH2  (NN * 32)            // half2 count of real rows
#define NH2P ((NN + 1) * 32)      // + one zero pad row (index NN)
#define LDS_PAD 72                // smem row stride (halves / floats)
#define NGRP ((NN + 63) / 64)     // 782 node-groups of 64
#define LBLK 592                  // 148 SMs x 4 resident blocks

// ---- scratch (device globals; no allocation allowed) ----
// g_ints: [0,NN) deg_out(edges), [NN,2NN) deg_in->padded len, [2NN] CSR alloc,
//         [2NN+1..2NN+3] per-layer work-steal counters (all zeroed by memset)
__device__ int     g_ints[2 * NN + 8];
__device__ int     g_off[NN];
__device__ int     g_cursor[NN];
__device__ int     g_csr_src[NEP];
__device__ float   g_norm_src[NN];
__device__ float   g_norm_dst[NN];
__device__ __align__(16) __half2 g_ha[NH2P];   // fp16 feature ping (row NN = zeros)
__device__ __align__(16) __half2 g_hb[NH2P];   // fp16 feature pong (row NN = zeros)
__device__ __align__(16) __half  g_wh[3 * DD * DD];  // fp16-converted gcn_w
__device__ float   g_xf[NM];       // final-layer fp32 output (FC input)

__device__ __forceinline__ float2 h2f_bits(float w) {
    unsigned u = __float_as_uint(w);
    __half2 h = *reinterpret_cast<__half2*>(&u);
    return __half22float2(h);
}

// ---------------------------------------------------------------------------
// 1. histogram edges (deg arrays pre-zeroed by memset)
__global__ void k_hist(const int* __restrict__ src, const int* __restrict__ dst) {
    int e = blockIdx.x * blockDim.x + threadIdx.x;
    if (e < EE) {
        atomicAdd(&g_ints[src[e]], 1);          // deg_out
        atomicAdd(&g_ints[NN + dst[e]], 1);     // deg_in
    }
}

// 2. per-node: norms (+1 self loop), padded CSR slot alloc, pad-fill with zero-row
//    index NN, bias init, zero pad feature rows, and fp16-convert gcn_w (once).
__global__ void k_build(const float* __restrict__ fc_b, float* __restrict__ out,
                        const float* __restrict__ gcn_w) {
    int i = blockIdx.x * blockDim.x + threadIdx.x;
    if (i < NN) {
        int dout = g_ints[i] + 1;
        int din  = g_ints[NN + i] + 1;          // entries incl. self loop
        g_norm_src[i] = rsqrtf((float)dout);
        g_norm_dst[i] = rsqrtf((float)din);
        int dpad = (din + 7) & ~7;
        int off = atomicAdd(&g_ints[2 * NN], dpad);
        g_off[i] = off;
        g_cursor[i] = off;
        g_ints[NN + i] = dpad;                  // repurpose: padded row length
        for (int p = off + din; p < off + dpad; p++) g_csr_src[p] = NN;
    }
    if (blockIdx.x == 0) {
        if (threadIdx.x < OUTK) out[threadIdx.x] = fc_b[threadIdx.x];
        if (threadIdx.x >= 32 && threadIdx.x < 64) {   // zero pad rows
            int l = threadIdx.x - 32;
            g_ha[NN * 32 + l] = __floats2half2_rn(0.f, 0.f);
            g_hb[NN * 32 + l] = __floats2half2_rn(0.f, 0.f);
        }
    }
    // blocks 100..147: convert 3*64*64 = 12288 W entries to fp16
    if (blockIdx.x >= 100 && blockIdx.x < 148) {
        int wi = (blockIdx.x - 100) * 256 + threadIdx.x;
        g_wh[wi] = __float2half(gcn_w[wi]);
    }
}

// 3. fused: scatter edges+loops into CSR, and premul F*norm_src -> fp16 ha
__global__ void k_scatpre(const int* __restrict__ src, const int* __restrict__ dst,
                          const float* __restrict__ F) {
    int i = blockIdx.x * blockDim.x + threadIdx.x;
    if (i < NE) {
        if (i < EE) {
            int d = dst[i];
            int p = atomicAdd(&g_cursor[d], 1);
            g_csr_src[p] = src[i];
        } else {
            int n = i - EE;
            int p = atomicAdd(&g_cursor[n], 1);
            g_csr_src[p] = n;
        }
    } else {
        int j = i - NE;                         // half2 index
        if (j < NH2) {
            float2 f = ((const float2*)F)[j];
            float ns = g_norm_src[j >> 5];
            g_ha[j] = __floats2half2_rn(f.x * ns, f.y * ns);
        }
    }
}

// 4. fused SpMM gather + HMMA GEMM + bias + relu. Persistent work-stealing:
//    LBLK blocks pull 64-node groups off an atomic counter (per-layer slot in
//    g_ints). W/bias loaded once per block; smem not unioned (37 KB, 4 blk/SM).
//    Gather: round-9 form — 4 rows per LDG.128, v[8] staging (32 lines in
//    flight per warp), shfl_xor(16,8) fold. Numerically identical to round 12.
template <bool HALF_OUT>
__global__ void __launch_bounds__(256) k_layer(
    const __half2* __restrict__ x2, const __half* __restrict__ Wh16,
    const float* __restrict__ b, __half2* __restrict__ yh, float* __restrict__ yf,
    int layer)
{
    __shared__ __half Wh[DD][LDS_PAD];
    __shared__ __half aggh[DD][LDS_PAD];
    __shared__ float  outS[DD][LDS_PAD];
    __shared__ float  bsh[DD];
    __shared__ int    gsh;

    int tid = threadIdx.x;
    int warp = tid >> 5, lane = tid & 31;

    // W tile: fp16 copy, vectorized uint2 (8B), loaded ONCE per block
    {
        const uint2* ws = (const uint2*)Wh16;
        for (int i = tid; i < DD * DD / 4; i += 256) {
            uint2 u = ws[i];
            *(uint2*)&Wh[i >> 4][(i * 4) & 63] = u;
        }
    }
    if (tid < DD) bsh[tid] = b[tid];

    const float4* xr = (const float4*)x2;      // row = 8 float4s (128 B)
    int rowgrp = lane >> 3;                    // 0..3
    int chunk  = lane & 7;                     // 16B column chunk
    int* ctr = &g_ints[2 * NN + 1 + layer];

    while (true) {
        if (tid == 0) gsh = atomicAdd(ctr, 1);
        __syncthreads();
        int gi = gsh;
        if (gi >= NGRP) break;
        int nodeBase = gi * 64;
        int group = nodeBase + warp * 8;

        // lane-parallel preload of this warp's 8 row offsets / padded lengths
        int offv = 0, lenv = 0;
        if (lane < 8 && group + lane < NN) {
            offv = g_off[group + lane];
            lenv = g_ints[NN + group + lane];
        }

        // ---- Phase A: gather (4 rows per LDG.128) ----
        #pragma unroll 1
        for (int it = 0; it < 8; it++) {
            int s0  = __shfl_sync(0xffffffffu, offv, it);
            int len = __shfl_sync(0xffffffffu, lenv, it);   // mult of 8 (0 if OOB)
            float2 a0 = {0.f, 0.f}, a1 = {0.f, 0.f}, a2 = {0.f, 0.f}, a3 = {0.f, 0.f};

            #pragma unroll 1
            for (int base = 0; base < len; base += 32) {
                int rem = len - base;
                int s = (lane < rem) ? g_csr_src[s0 + base + lane] : NN;
                int nb = (rem < 32 ? rem : 32) >> 2;        // 2,4,6,8 batches of 4
                float4 v[8];
                #pragma unroll
                for (int q = 0; q < 8; q++) {
                    int ss = __shfl_sync(0xffffffffu, s, q * 4 + rowgrp);
                    if (q < nb) v[q] = __ldg(&xr[ss * 8 + chunk]);
                }
                #pragma unroll
                for (int q = 0; q < 8; q++) {
                    if (q < nb) {
                        float4 f = v[q];
                        float2 f0 = h2f_bits(f.x), f1 = h2f_bits(f.y);
                        float2 f2 = h2f_bits(f.z), f3 = h2f_bits(f.w);
                        a0.x += f0.x; a0.y += f0.y;
                        a1.x += f1.x; a1.y += f1.y;
                        a2.x += f2.x; a2.y += f2.y;
                        a3.x += f3.x; a3.y += f3.y;
                    }
                }
            }
            // fold the 4 row-group partials (lanes c, c+8, c+16, c+24)
            #pragma unroll
            for (int st = 16; st >= 8; st >>= 1) {
                a0.x += __shfl_xor_sync(0xffffffffu, a0.x, st);
                a0.y += __shfl_xor_sync(0xffffffffu, a0.y, st);
                a1.x += __shfl_xor_sync(0xffffffffu, a1.x, st);
                a1.y += __shfl_xor_sync(0xffffffffu, a1.y, st);
                a2.x += __shfl_xor_sync(0xffffffffu, a2.x, st);
                a2.y += __shfl_xor_sync(0xffffffffu, a2.y, st);
                a3.x += __shfl_xor_sync(0xffffffffu, a3.x, st);
                a3.y += __shfl_xor_sync(0xffffffffu, a3.y, st);
            }
            int node = group + it;
            if (rowgrp == 0 && node < NN) {
                float nd = g_norm_dst[node];
                int local = warp * 8 + it;
                __half2* dp = (__half2*)&aggh[local][chunk * 8];
                dp[0] = __floats2half2_rn(a0.x * nd, a0.y * nd);
                dp[1] = __floats2half2_rn(a1.x * nd, a1.y * nd);
                dp[2] = __floats2half2_rn(a2.x * nd, a2.y * nd);
                dp[3] = __floats2half2_rn(a3.x * nd, a3.y * nd);
            }
        }
        __syncthreads();

        // ---- Phase B: 64x64x64 GEMM via HMMA ----
        int mi = warp >> 1;                // m-strip 0..3 (16 rows each)
        int n0 = (warp & 1) * 2;           // n-tile pair: tiles n0, n0+1

        wmma::fragment<wmma::accumulator, 16, 16, 16, float> cF0, cF1;
        wmma::fill_fragment(cF0, 0.f);
        wmma::fill_fragment(cF1, 0.f);
        #pragma unroll
        for (int k = 0; k < 4; k++) {
            wmma::fragment<wmma::matrix_a, 16, 16, 16, __half, wmma::row_major> aF;
            wmma::load_matrix_sync(aF, &aggh[mi * 16][k * 16], LDS_PAD);
            wmma::fragment<wmma::matrix_b, 16, 16, 16, __half, wmma::row_major> bF;
            wmma::load_matrix_sync(bF, &Wh[k * 16][n0 * 16], LDS_PAD);
            wmma::mma_sync(cF0, aF, bF, cF0);
            wmma::load_matrix_sync(bF, &Wh[k * 16][(n0 + 1) * 16], LDS_PAD);
            wmma::mma_sync(cF1, aF, bF, cF1);
        }
        // outS is separate smem (no union) -> store directly, then sync
        wmma::store_matrix_sync(&outS[mi * 16][n0 * 16], cF0, LDS_PAD,
                                wmma::mem_row_major);
        wmma::store_matrix_sync(&outS[mi * 16][(n0 + 1) * 16], cF1, LDS_PAD,
                                wmma::mem_row_major);
        __syncthreads();

        // ---- Phase C: epilogue ----
        int c0 = lane * 2;
        #pragma unroll 1
        for (int r = warp * 8; r < warp * 8 + 8; r++) {
            int node = nodeBase + r;
            if (node >= NN) break;
            float o0 = fmaxf(outS[r][c0]     + bsh[c0],     0.f);
            float o1 = fmaxf(outS[r][c0 + 1] + bsh[c0 + 1], 0.f);
            if (HALF_OUT) {
                float ns = g_norm_src[node];
                yh[node * 32 + lane] = __floats2half2_rn(o0 * ns, o1 * ns);
            } else {
                *(float2*)&yf[node * DD + c0] = make_float2(o0, o1);
            }
        }
        __syncthreads();   // aggh/outS fully consumed before next group
    }
}

// 5. out += fc_w @ relu(flat)   (DRAM-streaming GEMV; fc_w streamed evict-first;
//    exact-cover grid: one float4 column per thread)
__global__ void __launch_bounds__(256) k_fc(
    const float* __restrict__ fc_w, const float* __restrict__ xflat,
    float* __restrict__ out)
{
    __shared__ float sh[OUTK];
    if (threadIdx.x < OUTK) sh[threadIdx.x] = 0.f;
    __syncthreads();

    const int nv = NM / 4;  // 800000 float4s per output row
    float acc[OUTK];
    #pragma unroll
    for (int o = 0; o < OUTK; o++) acc[o] = 0.f;

    const float4* w4 = (const float4*)fc_w;
    const float4* x4 = (const float4*)xflat;
    int i = blockIdx.x * blockDim.x + threadIdx.x;
    if (i < nv) {
        float4 f = x4[i];
        f.x = fmaxf(f.x, 0.f); f.y = fmaxf(f.y, 0.f);
        f.z = fmaxf(f.z, 0.f); f.w = fmaxf(f.w, 0.f);
        #pragma unroll
        for (int o = 0; o < OUTK; o++) {
            float4 w = __ldcs(&w4[(size_t)o * nv + i]);
            acc[o] = fmaf(w.x, f.x, acc[o]);
            acc[o] = fmaf(w.y, f.y, acc[o]);
            acc[o] = fmaf(w.z, f.z, acc[o]);
            acc[o] = fmaf(w.w, f.w, acc[o]);
        }
    }

    #pragma unroll
    for (int o = 0; o < OUTK; o++) {
        float v = acc[o];
        #pragma unroll
        for (int s = 16; s; s >>= 1) v += __shfl_xor_sync(0xffffffffu, v, s);
        if ((threadIdx.x & 31) == 0) atomicAdd(&sh[o], v);
    }
    __syncthreads();
    if (threadIdx.x < OUTK) atomicAdd(&out[threadIdx.x], sh[threadIdx.x]);
}

// ---------------------------------------------------------------------------
extern "C" void kernel_launch(void* const* d_in, const int* in_sizes, int n_in,
                              void* d_out, int out_size)
{
    const float* F     = (const float*)d_in[0];
    const int*   src   = (const int*)d_in[1];
    const int*   dst   = (const int*)d_in[2];
    const float* gcn_w = (const float*)d_in[3];
    const float* gcn_b = (const float*)d_in[4];
    const float* fc_w  = (const float*)d_in[5];
    const float* fc_b  = (const float*)d_in[6];
    float* out = (float*)d_out;

    void* ints_addr;   cudaGetSymbolAddress(&ints_addr, g_ints);
    __half2* ha; cudaGetSymbolAddress((void**)&ha, g_ha);
    __half2* hb; cudaGetSymbolAddress((void**)&hb, g_hb);
    __half*  wh; cudaGetSymbolAddress((void**)&wh, g_wh);
    float*   xf; cudaGetSymbolAddress((void**)&xf, g_xf);

    // graph prep (memset also zeroes the 3 per-layer work counters)
    cudaMemsetAsync(ints_addr, 0, (2 * NN + 8) * sizeof(int));
    k_hist<<<(EE + 255) / 256, 256>>>(src, dst);
    k_build<<<(NN + 255) / 256, 256>>>(fc_b, out, gcn_w);
    k_scatpre<<<(NE + NH2 + 255) / 256, 256>>>(src, dst, F);

    // 3 GCN layers: ha -> hb -> ha -> xf (fp32); persistent work-stealing grids
    k_layer<true ><<<LBLK, 256>>>(ha, wh + 0 * DD * DD, gcn_b + 0 * DD, hb, nullptr, 0);
    k_layer<true ><<<LBLK, 256>>>(hb, wh + 1 * DD * DD, gcn_b + 1 * DD, ha, nullptr, 1);
    k_layer<false><<<LBLK, 256>>>(ha, wh + 2 * DD * DD, gcn_b + 2 * DD, nullptr, xf, 2);

    // FC head (exact cover: 3125*256 = 800000 threads)
    k_fc<<<3125, 256>>>(fc_w, xf, out);
}

// round 17
// speedup vs baseline: 7.5012x; 1.0478x over previous
#include <cuda_runtime.h>
#include <cuda_fp16.h>
#include <cstdint>
#include <mma.h>

using namespace nvcuda;

// Problem constants (GCN_48473000903499): N=50000, D=64, L=3, OUT=16, E=800000
#define NN   50000
#define DD   64
#define OUTK 16
#define EE   800000
#define NE   (EE + NN)            // edges + self loops = 850000
#define NEP  (NE + 7 * NN)        // CSR capacity with per-row pad-to-8
#define NM   (NN * DD)            // 3,200,000 flat elements
#define NH2  (NN * 32)            // half2 count of real rows
#define NH2P ((NN + 1) * 32)      // + one zero pad row (index NN)
#define LDS_PAD 72                // smem row stride (halves / floats)

// ---- scratch (device globals; no allocation allowed) ----
// g_ints: [0,NN) deg_out(edges), [NN,2NN) deg_in(edges)->padded row len, [2NN] alloc counter
__device__ int     g_ints[2 * NN + 1];
__device__ int     g_off[NN];
__device__ int     g_cursor[NN];
__device__ int     g_csr_src[NEP];
__device__ float   g_norm_src[NN];
__device__ float   g_norm_dst[NN];
__device__ __align__(16) __half2 g_ha[NH2P];   // fp16 feature ping (row NN = zeros)
__device__ __align__(16) __half2 g_hb[NH2P];   // fp16 feature pong (row NN = zeros)
__device__ __align__(16) __half  g_wh[3 * DD * DD];  // fp16-converted gcn_w
__device__ float   g_xf[NM];       // final-layer fp32 output (FC input)

__device__ __forceinline__ __half2 h2_bits(float w) {
    unsigned u = __float_as_uint(w);
    return *reinterpret_cast<__half2*>(&u);
}

// ---------------------------------------------------------------------------
// 1. histogram edges (deg arrays pre-zeroed by memset)
__global__ void k_hist(const int* __restrict__ src, const int* __restrict__ dst) {
    int e = blockIdx.x * blockDim.x + threadIdx.x;
    if (e < EE) {
        atomicAdd(&g_ints[src[e]], 1);          // deg_out
        atomicAdd(&g_ints[NN + dst[e]], 1);     // deg_in
    }
}

// 2. per-node: norms (+1 self loop), padded CSR slot alloc, pad-fill with zero-row
//    index NN, bias init, zero pad feature rows, and fp16-convert gcn_w (once).
__global__ void k_build(const float* __restrict__ fc_b, float* __restrict__ out,
                        const float* __restrict__ gcn_w) {
    int i = blockIdx.x * blockDim.x + threadIdx.x;
    if (i < NN) {
        int dout = g_ints[i] + 1;
        int din  = g_ints[NN + i] + 1;          // entries incl. self loop
        g_norm_src[i] = rsqrtf((float)dout);
        g_norm_dst[i] = rsqrtf((float)din);
        int dpad = (din + 7) & ~7;
        int off = atomicAdd(&g_ints[2 * NN], dpad);
        g_off[i] = off;
        g_cursor[i] = off;
        g_ints[NN + i] = dpad;                  // repurpose: padded row length
        for (int p = off + din; p < off + dpad; p++) g_csr_src[p] = NN;
    }
    if (blockIdx.x == 0) {
        if (threadIdx.x < OUTK) out[threadIdx.x] = fc_b[threadIdx.x];
        if (threadIdx.x >= 32 && threadIdx.x < 64) {   // zero pad rows
            int l = threadIdx.x - 32;
            g_ha[NN * 32 + l] = __floats2half2_rn(0.f, 0.f);
            g_hb[NN * 32 + l] = __floats2half2_rn(0.f, 0.f);
        }
    }
    // blocks 100..147: convert 3*64*64 = 12288 W entries to fp16
    if (blockIdx.x >= 100 && blockIdx.x < 148) {
        int wi = (blockIdx.x - 100) * 256 + threadIdx.x;
        g_wh[wi] = __float2half(gcn_w[wi]);
    }
}

// 3. fused: scatter edges+loops into CSR, and premul F*norm_src -> fp16 ha
__global__ void k_scatpre(const int* __restrict__ src, const int* __restrict__ dst,
                          const float* __restrict__ F) {
    int i = blockIdx.x * blockDim.x + threadIdx.x;
    if (i < NE) {
        if (i < EE) {
            int d = dst[i];
            int p = atomicAdd(&g_cursor[d], 1);
            g_csr_src[p] = src[i];
        } else {
            int n = i - EE;
            int p = atomicAdd(&g_cursor[n], 1);
            g_csr_src[p] = n;
        }
    } else {
        int j = i - NE;                         // half2 index
        if (j < NH2) {
            float2 f = ((const float2*)F)[j];
            float ns = g_norm_src[j >> 5];
            g_ha[j] = __floats2half2_rn(f.x * ns, f.y * ns);
        }
    }
}

// 4. fused SpMM gather + HMMA GEMM + bias + relu. 64 nodes/block, 8 warps,
//    grid-mapped (round-12 winner). Gather: 4 rows per LDG.128, v[8] staging
//    (32 lines in flight/warp); NEW: HADD2 fp16 accumulation within each
//    32-edge window (<=8-term fp16 chains), flushed to fp32 once per window.
//    Cuts per-window instr ~170 -> ~90.
struct SmemP1 { __half Wh[DD][LDS_PAD]; __half aggh[DD][LDS_PAD]; };
union  SmemU  { SmemP1 p1; float outS[DD][LDS_PAD]; };

template <bool HALF_OUT>
__global__ void __launch_bounds__(256) k_layer(
    const __half2* __restrict__ x2, const __half* __restrict__ Wh16,
    const float* __restrict__ b, __half2* __restrict__ yh, float* __restrict__ yf)
{
    __shared__ SmemU sm;
    __shared__ float bsh[DD];

    int tid = threadIdx.x;
    int warp = tid >> 5, lane = tid & 31;
    int nodeBase = blockIdx.x * 64;

    // W tile: fp16 copy, vectorized uint2 (8B) to respect padded row stride
    {
        const uint2* ws = (const uint2*)Wh16;
        for (int i = tid; i < DD * DD / 4; i += 256) {
            uint2 u = ws[i];
            *(uint2*)&sm.p1.Wh[i >> 4][(i * 4) & 63] = u;
        }
    }
    if (tid < DD) bsh[tid] = b[tid];

    // lane-parallel preload of this warp's 8 row offsets / padded lengths
    int group = nodeBase + warp * 8;
    int offv = 0, lenv = 0;
    if (lane < 8 && group + lane < NN) {
        offv = g_off[group + lane];
        lenv = g_ints[NN + group + lane];
    }
    __syncthreads();

    // ---- Phase A: gather (4 rows per LDG.128, HADD2 window accumulation) ----
    const float4* xr = (const float4*)x2;      // row = 8 float4s (128 B)
    int rowgrp = lane >> 3;                    // 0..3
    int chunk  = lane & 7;                     // 16B column chunk
    #pragma unroll 1
    for (int it = 0; it < 8; it++) {
        int s0  = __shfl_sync(0xffffffffu, offv, it);
        int len = __shfl_sync(0xffffffffu, lenv, it);   // multiple of 8 (0 if OOB)
        float2 a0 = {0.f, 0.f}, a1 = {0.f, 0.f}, a2 = {0.f, 0.f}, a3 = {0.f, 0.f};

        #pragma unroll 1
        for (int base = 0; base < len; base += 32) {
            int rem = len - base;
            int s = (lane < rem) ? g_csr_src[s0 + base + lane] : NN;
            int nb = (rem < 32 ? rem : 32) >> 2;        // 2,4,6,8 batches of 4 rows
            float4 v[8];
            #pragma unroll
            for (int q = 0; q < 8; q++) {
                int ss = __shfl_sync(0xffffffffu, s, q * 4 + rowgrp);
                if (q < nb) v[q] = __ldg(&xr[ss * 8 + chunk]);
            }
            // fp16 accumulation within this window (chain length <= 8)
            __half2 h0 = __floats2half2_rn(0.f, 0.f);
            __half2 h1 = h0, h2 = h0, h3 = h0;
            #pragma unroll
            for (int q = 0; q < 8; q++) {
                if (q < nb) {
                    float4 f = v[q];
                    h0 = __hadd2(h0, h2_bits(f.x));
                    h1 = __hadd2(h1, h2_bits(f.y));
                    h2 = __hadd2(h2, h2_bits(f.z));
                    h3 = __hadd2(h3, h2_bits(f.w));
                }
            }
            // flush window partials into fp32 running totals
            float2 f0 = __half22float2(h0), f1 = __half22float2(h1);
            float2 f2 = __half22float2(h2), f3 = __half22float2(h3);
            a0.x += f0.x; a0.y += f0.y;
            a1.x += f1.x; a1.y += f1.y;
            a2.x += f2.x; a2.y += f2.y;
            a3.x += f3.x; a3.y += f3.y;
        }
        // fold the 4 row-group partials (lanes c, c+8, c+16, c+24)
        #pragma unroll
        for (int st = 16; st >= 8; st >>= 1) {
            a0.x += __shfl_xor_sync(0xffffffffu, a0.x, st);
            a0.y += __shfl_xor_sync(0xffffffffu, a0.y, st);
            a1.x += __shfl_xor_sync(0xffffffffu, a1.x, st);
            a1.y += __shfl_xor_sync(0xffffffffu, a1.y, st);
            a2.x += __shfl_xor_sync(0xffffffffu, a2.x, st);
            a2.y += __shfl_xor_sync(0xffffffffu, a2.y, st);
            a3.x += __shfl_xor_sync(0xffffffffu, a3.x, st);
            a3.y += __shfl_xor_sync(0xffffffffu, a3.y, st);
        }
        int node = group + it;
        if (rowgrp == 0 && node < NN) {
            float nd = g_norm_dst[node];
            int local = warp * 8 + it;
            __half2* dp = (__half2*)&sm.p1.aggh[local][chunk * 8];
            dp[0] = __floats2half2_rn(a0.x * nd, a0.y * nd);
            dp[1] = __floats2half2_rn(a1.x * nd, a1.y * nd);
            dp[2] = __floats2half2_rn(a2.x * nd, a2.y * nd);
            dp[3] = __floats2half2_rn(a3.x * nd, a3.y * nd);
        }
    }
    __syncthreads();

    // ---- Phase B: 64x64x64 GEMM via HMMA (C kept in regs across barrier) ----
    int mi = warp >> 1;                // m-strip 0..3 (16 rows each)
    int n0 = (warp & 1) * 2;           // n-tile pair: tiles n0, n0+1

    wmma::fragment<wmma::accumulator, 16, 16, 16, float> cF0, cF1;
    wmma::fill_fragment(cF0, 0.f);
    wmma::fill_fragment(cF1, 0.f);
    #pragma unroll
    for (int k = 0; k < 4; k++) {
        wmma::fragment<wmma::matrix_a, 16, 16, 16, __half, wmma::row_major> aF;
        wmma::load_matrix_sync(aF, &sm.p1.aggh[mi * 16][k * 16], LDS_PAD);
        wmma::fragment<wmma::matrix_b, 16, 16, 16, __half, wmma::row_major> bF;
        wmma::load_matrix_sync(bF, &sm.p1.Wh[k * 16][n0 * 16], LDS_PAD);
        wmma::mma_sync(cF0, aF, bF, cF0);
        wmma::load_matrix_sync(bF, &sm.p1.Wh[k * 16][(n0 + 1) * 16], LDS_PAD);
        wmma::mma_sync(cF1, aF, bF, cF1);
    }
    __syncthreads();    // everyone done reading Wh/aggh; smem now becomes outS
    wmma::store_matrix_sync(&sm.outS[mi * 16][n0 * 16], cF0, LDS_PAD,
                            wmma::mem_row_major);
    wmma::store_matrix_sync(&sm.outS[mi * 16][(n0 + 1) * 16], cF1, LDS_PAD,
                            wmma::mem_row_major);
    __syncthreads();

    // ---- Phase C: epilogue ----
    int c0 = lane * 2;
    #pragma unroll 1
    for (int r = warp * 8; r < warp * 8 + 8; r++) {
        int node = nodeBase + r;
        if (node >= NN) break;
        float o0 = fmaxf(sm.outS[r][c0]     + bsh[c0],     0.f);
        float o1 = fmaxf(sm.outS[r][c0 + 1] + bsh[c0 + 1], 0.f);
        if (HALF_OUT) {
            float ns = g_norm_src[node];
            yh[node * 32 + lane] = __floats2half2_rn(o0 * ns, o1 * ns);
        } else {
            *(float2*)&yf[node * DD + c0] = make_float2(o0, o1);
        }
    }
}

// 5. out += fc_w @ relu(flat)   (DRAM-streaming GEMV; fc_w streamed evict-first;
//    exact-cover grid: one float4 column per thread — round-16 winner)
__global__ void __launch_bounds__(256) k_fc(
    const float* __restrict__ fc_w, const float* __restrict__ xflat,
    float* __restrict__ out)
{
    __shared__ float sh[OUTK];
    if (threadIdx.x < OUTK) sh[threadIdx.x] = 0.f;
    __syncthreads();

    const int nv = NM / 4;  // 800000 float4s per output row
    float acc[OUTK];
    #pragma unroll
    for (int o = 0; o < OUTK; o++) acc[o] = 0.f;

    const float4* w4 = (const float4*)fc_w;
    const float4* x4 = (const float4*)xflat;
    int i = blockIdx.x * blockDim.x + threadIdx.x;
    if (i < nv) {
        float4 f = x4[i];
        f.x = fmaxf(f.x, 0.f); f.y = fmaxf(f.y, 0.f);
        f.z = fmaxf(f.z, 0.f); f.w = fmaxf(f.w, 0.f);
        #pragma unroll
        for (int o = 0; o < OUTK; o++) {
            float4 w = __ldcs(&w4[(size_t)o * nv + i]);
            acc[o] = fmaf(w.x, f.x, acc[o]);
            acc[o] = fmaf(w.y, f.y, acc[o]);
            acc[o] = fmaf(w.z, f.z, acc[o]);
            acc[o] = fmaf(w.w, f.w, acc[o]);
        }
    }

    #pragma unroll
    for (int o = 0; o < OUTK; o++) {
        float v = acc[o];
        #pragma unroll
        for (int s = 16; s; s >>= 1) v += __shfl_xor_sync(0xffffffffu, v, s);
        if ((threadIdx.x & 31) == 0) atomicAdd(&sh[o], v);
    }
    __syncthreads();
    if (threadIdx.x < OUTK) atomicAdd(&out[threadIdx.x], sh[threadIdx.x]);
}

// ---------------------------------------------------------------------------
extern "C" void kernel_launch(void* const* d_in, const int* in_sizes, int n_in,
                              void* d_out, int out_size)
{
    const float* F     = (const float*)d_in[0];
    const int*   src   = (const int*)d_in[1];
    const int*   dst   = (const int*)d_in[2];
    const float* gcn_w = (const float*)d_in[3];
    const float* gcn_b = (const float*)d_in[4];
    const float* fc_w  = (const float*)d_in[5];
    const float* fc_b  = (const float*)d_in[6];
    float* out = (float*)d_out;

    void* ints_addr;   cudaGetSymbolAddress(&ints_addr, g_ints);
    __half2* ha; cudaGetSymbolAddress((void**)&ha, g_ha);
    __half2* hb; cudaGetSymbolAddress((void**)&hb, g_hb);
    __half*  wh; cudaGetSymbolAddress((void**)&wh, g_wh);
    float*   xf; cudaGetSymbolAddress((void**)&xf, g_xf);

    // graph prep
    cudaMemsetAsync(ints_addr, 0, (2 * NN + 1) * sizeof(int));
    k_hist<<<(EE + 255) / 256, 256>>>(src, dst);
    k_build<<<(NN + 255) / 256, 256>>>(fc_b, out, gcn_w);
    k_scatpre<<<(NE + NH2 + 255) / 256, 256>>>(src, dst, F);

    // 3 GCN layers: ha -> hb -> ha -> xf (fp32)
    const int lblocks = (NN + 63) / 64;
    k_layer<true ><<<lblocks, 256>>>(ha, wh + 0 * DD * DD, gcn_b + 0 * DD, hb, nullptr);
    k_layer<true ><<<lblocks, 256>>>(hb, wh + 1 * DD * DD, gcn_b + 1 * DD, ha, nullptr);
    k_layer<false><<<lblocks, 256>>>(ha, wh + 2 * DD * DD, gcn_b + 2 * DD, nullptr, xf);

    // FC head (exact cover: 3125*256 = 800000 threads)
    k_fc<<<3125, 256>>>(fc_w, xf, out);
}